// round 14
// baseline (speedup 1.0000x reference)
#include <cuda_runtime.h>
#include <cstdint>

#define KNB   32
#define KP    15
#define CIN   64
#define COUT  128
#define KTOT  (KP * CIN)     // 960
#define NMAX  65536
#define INV_SIGMA 10.0f

typedef unsigned long long u64;
typedef unsigned int u32;

__device__ float g_weighted[(size_t)NMAX * KTOT];   // 240MB scratch (tf32-rounded)
__device__ float g_Wt[COUT * KTOT];                 // W transposed [n][k], tf32-rounded

__device__ __forceinline__ void fma2(u64& d, u64 a, u64 b) {
    asm("fma.rn.f32x2 %0, %1, %2, %0;" : "+l"(d) : "l"(a), "l"(b));
}
__device__ __forceinline__ u64 pack2(float lo, float hi) {
    u64 r;
    asm("mov.b64 %0, {%1, %2};" : "=l"(r) : "r"(__float_as_uint(lo)), "r"(__float_as_uint(hi)));
    return r;
}
__device__ __forceinline__ u32 tf32r(float x) {
    u32 r;
    asm("cvt.rna.tf32.f32 %0, %1;" : "=r"(r) : "f"(x));
    return r;
}
__device__ __forceinline__ u32 smem_u32(const void* p) {
    u32 a;
    asm("{ .reg .u64 t; cvta.to.shared.u64 t, %1; cvt.u32.u64 %0, t; }" : "=r"(a) : "l"(p));
    return a;
}
__device__ __forceinline__ void cp16(u32 dst, const void* src) {
    asm volatile("cp.async.cg.shared.global [%0], [%1], 16;" :: "r"(dst), "l"(src));
}
__device__ __forceinline__ void mma_tf32(float* c, u32 a0, u32 a1, u32 a2, u32 a3,
                                         u32 b0, u32 b1) {
    asm("mma.sync.aligned.m16n8k8.row.col.f32.tf32.tf32.f32 "
        "{%0,%1,%2,%3}, {%4,%5,%6,%7}, {%8,%9}, {%0,%1,%2,%3};"
        : "+f"(c[0]), "+f"(c[1]), "+f"(c[2]), "+f"(c[3])
        : "r"(a0), "r"(a1), "r"(a2), "r"(a3), "r"(b0), "r"(b1));
}

// ------------------------------------------------------------ W transpose (+tf32 round)
__global__ void wt_kernel(const float* __restrict__ W) {
    int i = blockIdx.x * 256 + threadIdx.x;     // over KTOT*COUT
    if (i < KTOT * COUT) {
        int k = i >> 7;          // KTOT index
        int n = i & 127;         // COUT index
        ((u32*)g_Wt)[n * KTOT + k] = tf32r(W[i]);
    }
}

// ---------------------------------------------------------------- stage 1+2
// 8 warps = 4 points/block; 2 warps per point (c-halves of 32).
// infl stored transposed: sInfl[pt][j*20 + kp] (stride 20 floats: STS.128 and
// LDS.128 conflict-free, bank(20j+4q) covers all 32 banks per 8-lane phase).
// Aggregation: lane owns c = half*32+lane. acc[a] = (kp 2a, kp 2a+1) pairs;
// one LDS.128 (uniform broadcast) feeds 2 FFMA2 with NO dup MOVs; the
// duplicated operand is {f,f}, loaded once per j (coalesced LDG.32, 8-deep
// prefetch) and reused across all 8 kp-pairs.
#define S12P  4     // points per block
#define ROWF  20    // floats per j-row (15 infl + pad)

__global__ void __launch_bounds__(256)
stage12_kernel(const float* __restrict__ pos,
               const float* __restrict__ feats,
               const float* __restrict__ kpts,
               const void*  __restrict__ nbrs,
               int N)
{
    __shared__ __align__(16) float sInfl[S12P][KNB * ROWF];   // 10240B
    __shared__ float sKP[KP * 3];
    __shared__ int   sNbr[S12P][KNB];
    __shared__ int   sIs64;

    const int tid  = threadIdx.x;
    const int w    = tid >> 5;
    const int lane = tid & 31;
    const int p    = w >> 1;      // point within block
    const int half = w & 1;       // c-half

    if (tid < KP * 3) sKP[tid] = kpts[tid];
    if (tid == 0) {
        // indices < 2^16: int64 little-endian => odd 32-bit words are 0
        const int* q = (const int*)nbrs;
        int zeros = 0;
#pragma unroll
        for (int i = 0; i < 32; i++) zeros += (q[2 * i + 1] == 0) ? 1 : 0;
        sIs64 = (zeros >= 30) ? 1 : 0;
    }
    __syncthreads();

    const int n = blockIdx.x * S12P + p;

    // ---- geometry (warp-half 0 only): lane = neighbor j
    if (n < N && half == 0) {
        const int j = lane;
        int nbi;
        if (sIs64) nbi = (int)((const long long*)nbrs)[(long long)n * KNB + j];
        else       nbi = ((const int*)nbrs)[n * KNB + j];
        sNbr[p][j] = nbi;

        const float rx = pos[3 * nbi + 0] - pos[3 * n + 0];
        const float ry = pos[3 * nbi + 1] - pos[3 * n + 1];
        const float rz = pos[3 * nbi + 2] - pos[3 * n + 2];
        float v[16];
#pragma unroll
        for (int kp = 0; kp < KP; kp++) {
            const float dx = rx - sKP[3 * kp + 0];
            const float dy = ry - sKP[3 * kp + 1];
            const float dz = rz - sKP[3 * kp + 2];
            const float dist = sqrtf(dx * dx + dy * dy + dz * dz);
            v[kp] = fmaxf(0.0f, 1.0f - dist * INV_SIGMA);
        }
        v[15] = 0.0f;
        float* row = &sInfl[p][j * ROWF];
#pragma unroll
        for (int q4 = 0; q4 < 4; q4++)
            *(float4*)(row + q4 * 4) = make_float4(v[q4 * 4], v[q4 * 4 + 1],
                                                   v[q4 * 4 + 2], v[q4 * 4 + 3]);
    }
    __syncthreads();
    if (n >= N) return;

    // ---- aggregation: lane owns channel co
    const int co = half * 32 + lane;

    u64 acc[8];
#pragma unroll
    for (int a = 0; a < 8; a++) acc[a] = 0ULL;

    float fbuf[8];
#pragma unroll
    for (int i = 0; i < 8; i++)
        fbuf[i] = feats[(size_t)sNbr[p][i] * CIN + co];

    for (int jc = 0; jc < 4; jc++) {
        float fnext[8];
        if (jc < 3) {
#pragma unroll
            for (int i = 0; i < 8; i++)
                fnext[i] = feats[(size_t)sNbr[p][jc * 8 + 8 + i] * CIN + co];
        }
#pragma unroll
        for (int i = 0; i < 8; i++) {
            const int j = jc * 8 + i;
            const u64 fd = pack2(fbuf[i], fbuf[i]);
            const float4* row = (const float4*)&sInfl[p][j * ROWF];
#pragma unroll
            for (int q4 = 0; q4 < 4; q4++) {
                const float4 iv = row[q4];             // broadcast LDS.128
                fma2(acc[2 * q4 + 0], pack2(iv.x, iv.y), fd);
                fma2(acc[2 * q4 + 1], pack2(iv.z, iv.w), fd);
            }
        }
        if (jc < 3) {
#pragma unroll
            for (int i = 0; i < 8; i++) fbuf[i] = fnext[i];
        }
    }

    // ---- store tf32-rounded: acc[a] = (kp 2a, kp 2a+1); kp 15 is pad
    u32* gp = (u32*)(g_weighted + (size_t)n * KTOT + co);
#pragma unroll
    for (int a = 0; a < 8; a++) {
        const u32 lo = tf32r(__uint_as_float((u32)(acc[a] & 0xFFFFFFFFULL)));
        gp[(2 * a) * CIN] = lo;
        if (a < 7) {
            const u32 hi = tf32r(__uint_as_float((u32)(acc[a] >> 32)));
            gp[(2 * a + 1) * CIN] = hi;
        }
    }
}

// ------------------------------------------------------------------ stage 3
// out[N,128] = g_weighted[N,960] @ g_Wt^T via mma.sync m16n8k8 tf32.
// CTA 128x128, K in 30 chunks of 32; 3-stage cp.async smem pipeline.
// Tiles row-major with row stride 36 floats: bank(row*36+k) = (4*row+k)%32,
// bijective over the fragment lanes (r<8, q<4) -> all LDS.32 conflict-free.
#define NC    30
#define RSTR  36                 // row stride (floats)
#define TILE_F (128 * RSTR)      // floats per tile
#define STG_F  (2 * TILE_F)      // A + B per stage
#define STG_B  (STG_F * 4)       // 36864 bytes
#define SMEM3  (3 * STG_B)       // 110592 bytes

__global__ void __launch_bounds__(256, 2)
stage3_hmma(float* __restrict__ out, int N)
{
    extern __shared__ float sm[];
    const u32 sbase = smem_u32(sm);
    const int tid  = threadIdx.x;
    const int w    = tid >> 5;
    const int lane = tid & 31;
    const int wm   = (w & 1) * 64;
    const int wn   = (w >> 1) * 32;
    const int m0   = blockIdx.x * 128;
    const int q    = lane & 3;
    const int r    = lane >> 2;

    const float* Ag = g_weighted + (size_t)m0 * KTOT;

    auto issue = [&](int ck, int buf) {
        const u32 ab = sbase + buf * STG_B;
        const u32 bb = ab + TILE_F * 4;
#pragma unroll
        for (int i = 0; i < 4; i++) {
            const int id  = tid + i * 256;
            const int row = id >> 3;
            const int s4  = id & 7;
            cp16(ab + row * (RSTR * 4) + s4 * 16,
                 Ag + (size_t)row * KTOT + ck * 32 + s4 * 4);
            cp16(bb + row * (RSTR * 4) + s4 * 16,
                 g_Wt + (size_t)row * KTOT + ck * 32 + s4 * 4);
        }
    };

    float acc[4][4][4];
#pragma unroll
    for (int mt = 0; mt < 4; mt++)
#pragma unroll
        for (int nt = 0; nt < 4; nt++)
#pragma unroll
            for (int p = 0; p < 4; p++) acc[mt][nt][p] = 0.0f;

    issue(0, 0);
    asm volatile("cp.async.commit_group;" ::: "memory");
    issue(1, 1);
    asm volatile("cp.async.commit_group;" ::: "memory");

    for (int c = 0; c < NC; c++) {
        asm volatile("cp.async.wait_group 1;" ::: "memory");
        __syncthreads();

        const float* sA = sm + (c % 3) * STG_F;
        const float* sB = sA + TILE_F;

#pragma unroll
        for (int s = 0; s < 4; s++) {
            const int k0 = s * 8;
            u32 a[4][4];
#pragma unroll
            for (int mt = 0; mt < 4; mt++) {
                const int r0 = wm + mt * 16 + r;
                a[mt][0] = __float_as_uint(sA[r0 * RSTR + k0 + q]);
                a[mt][1] = __float_as_uint(sA[(r0 + 8) * RSTR + k0 + q]);
                a[mt][2] = __float_as_uint(sA[r0 * RSTR + k0 + q + 4]);
                a[mt][3] = __float_as_uint(sA[(r0 + 8) * RSTR + k0 + q + 4]);
            }
#pragma unroll
            for (int nt = 0; nt < 4; nt++) {
                const int n = wn + nt * 8 + r;
                const u32 b0 = __float_as_uint(sB[n * RSTR + k0 + q]);
                const u32 b1 = __float_as_uint(sB[n * RSTR + k0 + q + 4]);
#pragma unroll
                for (int mt = 0; mt < 4; mt++)
                    mma_tf32(acc[mt][nt], a[mt][0], a[mt][1], a[mt][2], a[mt][3],
                             b0, b1);
            }
        }

        if (c + 2 < NC) issue(c + 2, (c + 2) % 3);
        asm volatile("cp.async.commit_group;" ::: "memory");
    }

    // epilogue: c0,c1 -> (row, 2c+{0,1}); c2,c3 -> row+8
#pragma unroll
    for (int mt = 0; mt < 4; mt++) {
        const int r0 = m0 + wm + mt * 16 + r;
#pragma unroll
        for (int nt = 0; nt < 4; nt++) {
            const int n = wn + nt * 8 + 2 * q;
            if (r0 < N)
                *(float2*)(out + (size_t)r0 * COUT + n) =
                    make_float2(acc[mt][nt][0], acc[mt][nt][1]);
            if (r0 + 8 < N)
                *(float2*)(out + (size_t)(r0 + 8) * COUT + n) =
                    make_float2(acc[mt][nt][2], acc[mt][nt][3]);
        }
    }
}

extern "C" void kernel_launch(void* const* d_in, const int* in_sizes, int n_in,
                              void* d_out, int out_size)
{
    const float* pos   = (const float*)d_in[0];
    const float* feats = (const float*)d_in[1];
    const float* kpts  = (const float*)d_in[2];
    const float* W     = (const float*)d_in[3];
    const void*  nbrs  = d_in[4];
    float* out = (float*)d_out;

    const int N = in_sizes[1] / CIN;   // feats is [N, CIN]

    cudaFuncSetAttribute(stage3_hmma,
                         cudaFuncAttributeMaxDynamicSharedMemorySize, SMEM3);

    // order: stage12 first so ncu's fixed launch-skip samples it
    stage12_kernel<<<(N + S12P - 1) / S12P, 256>>>(pos, feats, kpts, nbrs, N);

    wt_kernel<<<(KTOT * COUT + 255) / 256, 256>>>(W);

    stage3_hmma<<<(N + 127) / 128, 256, SMEM3>>>(out, N);
}

// round 15
// speedup vs baseline: 1.5676x; 1.5676x over previous
#include <cuda_runtime.h>
#include <cuda_fp16.h>
#include <cstdint>

#define KNB   32
#define KP    15
#define CIN   64
#define COUT  128
#define KTOT  (KP * CIN)     // 960
#define NMAX  65536
#define INV_SIGMA 10.0f

typedef unsigned long long u64;
typedef unsigned int u32;

__device__ __half g_wh[(size_t)NMAX * KTOT];   // weighted, fp16 (120MB)
__device__ __half g_Wth[COUT * KTOT];          // W transposed [n][k], fp16

__device__ __forceinline__ void fma2(u64& d, u64 a, u64 b) {
    asm("fma.rn.f32x2 %0, %1, %2, %0;" : "+l"(d) : "l"(a), "l"(b));
}
__device__ __forceinline__ u64 dup2(u32 x) {
    u64 r;
    asm("mov.b64 %0, {%1, %1};" : "=l"(r) : "r"(x));
    return r;
}
__device__ __forceinline__ float lo32f(u64 v) { return __uint_as_float((u32)v); }
__device__ __forceinline__ float hi32f(u64 v) { return __uint_as_float((u32)(v >> 32)); }
__device__ __forceinline__ u32 smem_u32(const void* p) {
    u32 a;
    asm("{ .reg .u64 t; cvta.to.shared.u64 t, %1; cvt.u32.u64 %0, t; }" : "=r"(a) : "l"(p));
    return a;
}
__device__ __forceinline__ void cp16(u32 dst, const void* src) {
    asm volatile("cp.async.cg.shared.global [%0], [%1], 16;" :: "r"(dst), "l"(src));
}
__device__ __forceinline__ void mma_f16(float* c, u32 a0, u32 a1, u32 a2, u32 a3,
                                        u32 b0, u32 b1) {
    asm("mma.sync.aligned.m16n8k16.row.col.f32.f16.f16.f32 "
        "{%0,%1,%2,%3}, {%4,%5,%6,%7}, {%8,%9}, {%0,%1,%2,%3};"
        : "+f"(c[0]), "+f"(c[1]), "+f"(c[2]), "+f"(c[3])
        : "r"(a0), "r"(a1), "r"(a2), "r"(a3), "r"(b0), "r"(b1));
}

// ------------------------------------------------------------ W transpose -> fp16
__global__ void wt_kernel(const float* __restrict__ W) {
    int i = blockIdx.x * 256 + threadIdx.x;     // over KTOT*COUT
    if (i < KTOT * COUT) {
        int k = i >> 7;          // KTOT index
        int n = i & 127;         // COUT index
        g_Wth[n * KTOT + k] = __float2half(W[i]);
    }
}

// ---------------------------------------------------------------- stage 1+2
// R13 structure: 8 warps = 8 points/block, lane owns c-pair {2l, 2l+1}.
// sInfl: per point 32 rows (j) of 16 floats (15 infl + pad0), row stride 20.
// Inner loop per j: 1 LDG.64 (feats c-pair) + 2 dup MOVs + 4 LDS.128
// (ulonglong2 -> register-adjacent kp-pair u64s, NO repacking) + 16 FFMA2.
// acc[a][ch]: halves = (kp 2a, kp 2a+1) at channel ch.
#define ROWF 20

__global__ void __launch_bounds__(256)
stage12_kernel(const float* __restrict__ pos,
               const float* __restrict__ feats,
               const float* __restrict__ kpts,
               const void*  __restrict__ nbrs,
               int N)
{
    __shared__ __align__(16) float sInfl[8][KNB * ROWF];   // 20KB
    __shared__ float sKP[KP * 3];
    __shared__ int   sNbr[8][KNB];
    __shared__ int   sIs64;

    const int tid  = threadIdx.x;
    const int wid  = tid >> 5;
    const int lane = tid & 31;

    if (tid < KP * 3) sKP[tid] = kpts[tid];
    if (tid == 0) {
        // indices < 2^16: int64 little-endian => odd 32-bit words are 0
        const int* q = (const int*)nbrs;
        int zeros = 0;
#pragma unroll
        for (int i = 0; i < 32; i++) zeros += (q[2 * i + 1] == 0) ? 1 : 0;
        sIs64 = (zeros >= 30) ? 1 : 0;
    }
    __syncthreads();

    const int n = blockIdx.x * 8 + wid;
    if (n >= N) return;

    // ---- geometry: lane = neighbor j
    int nbi;
    if (sIs64) nbi = (int)((const long long*)nbrs)[(long long)n * KNB + lane];
    else       nbi = ((const int*)nbrs)[n * KNB + lane];
    sNbr[wid][lane] = nbi;

    const float rx = pos[3 * nbi + 0] - pos[3 * n + 0];
    const float ry = pos[3 * nbi + 1] - pos[3 * n + 1];
    const float rz = pos[3 * nbi + 2] - pos[3 * n + 2];
    float v[16];
#pragma unroll
    for (int kp = 0; kp < KP; kp++) {
        const float dx = rx - sKP[3 * kp + 0];
        const float dy = ry - sKP[3 * kp + 1];
        const float dz = rz - sKP[3 * kp + 2];
        const float dist = sqrtf(dx * dx + dy * dy + dz * dz);
        v[kp] = fmaxf(0.0f, 1.0f - dist * INV_SIGMA);
    }
    v[15] = 0.0f;
    {
        float* row = &sInfl[wid][lane * ROWF];
#pragma unroll
        for (int q4 = 0; q4 < 4; q4++)
            *(float4*)(row + q4 * 4) =
                make_float4(v[q4 * 4], v[q4 * 4 + 1], v[q4 * 4 + 2], v[q4 * 4 + 3]);
    }
    __syncwarp();

    // ---- aggregation
    u64 acc[8][2];
#pragma unroll
    for (int a = 0; a < 8; a++) { acc[a][0] = 0ULL; acc[a][1] = 0ULL; }

#pragma unroll 4
    for (int j = 0; j < KNB; j++) {
        const int nb = sNbr[wid][j];
        const u64 f = *(const u64*)(feats + (size_t)nb * CIN + 2 * lane);
        const u64 f0 = dup2((u32)f);          // {f_c0, f_c0}
        const u64 f1 = dup2((u32)(f >> 32));  // {f_c1, f_c1}
        const ulonglong2* rp = (const ulonglong2*)&sInfl[wid][j * ROWF];
#pragma unroll
        for (int q4 = 0; q4 < 4; q4++) {
            const ulonglong2 iv = rp[q4];     // broadcast LDS.128
            fma2(acc[2 * q4 + 0][0], iv.x, f0);
            fma2(acc[2 * q4 + 0][1], iv.x, f1);
            fma2(acc[2 * q4 + 1][0], iv.y, f0);
            fma2(acc[2 * q4 + 1][1], iv.y, f1);
        }
    }

    // ---- store fp16: kp=2a from lo halves, kp=2a+1 from hi halves
    __half* gp = g_wh + (size_t)n * KTOT + 2 * lane;
#pragma unroll
    for (int a = 0; a < 8; a++) {
        const __half2 h0 = __floats2half2_rn(lo32f(acc[a][0]), lo32f(acc[a][1]));
        *(__half2*)(gp + (2 * a) * CIN) = h0;
        if (a < 7) {
            const __half2 h1 = __floats2half2_rn(hi32f(acc[a][0]), hi32f(acc[a][1]));
            *(__half2*)(gp + (2 * a + 1) * CIN) = h1;
        }
    }
}

// ------------------------------------------------------------------ stage 3
// out[N,128] = g_wh[N,960] @ g_Wth^T via mma.sync m16n8k16 fp16 (f32 accum).
// CTA 128x128, K in 30 chunks of 32 halves; 3-stage cp.async pipeline.
// Tiles: 128 rows x 32 halves, row stride 40 halves (80B). Fragment half2
// loads hit bank (20*row + q + 8*s) — bijective over (r<8, q<4): conflict-free.
#define NC     30
#define RSTRH  40                 // row stride (halves)
#define TILE_B (128 * RSTRH * 2)  // bytes per tile (10240)
#define STG_B  (2 * TILE_B)       // A + B per stage (20480)
#define SMEM3  (3 * STG_B)        // 61440

__global__ void __launch_bounds__(256, 2)
stage3_hmma(float* __restrict__ out, int N)
{
    extern __shared__ __half smh[];
    const u32 sbase = smem_u32(smh);
    const int tid  = threadIdx.x;
    const int w    = tid >> 5;
    const int lane = tid & 31;
    const int wm   = (w & 1) * 64;
    const int wn   = (w >> 1) * 32;
    const int m0   = blockIdx.x * 128;
    const int q    = lane & 3;
    const int r    = lane >> 2;

    const __half* Agh = g_wh + (size_t)m0 * KTOT;

    // per chunk: A = 128 rows x 64B = 512 x 16B; 2 cp16/thread each for A and B
    auto issue = [&](int ck, int buf) {
        const u32 ab = sbase + buf * STG_B;
        const u32 bb = ab + TILE_B;
#pragma unroll
        for (int i = 0; i < 2; i++) {
            const int id  = tid + i * 256;
            const int row = id >> 2;
            const int s4  = id & 3;
            cp16(ab + row * (RSTRH * 2) + s4 * 16,
                 Agh + (size_t)row * KTOT + ck * 32 + s4 * 8);
            cp16(bb + row * (RSTRH * 2) + s4 * 16,
                 g_Wth + (size_t)row * KTOT + ck * 32 + s4 * 8);
        }
    };

    float acc[4][4][4];
#pragma unroll
    for (int mt = 0; mt < 4; mt++)
#pragma unroll
        for (int nt = 0; nt < 4; nt++)
#pragma unroll
            for (int p = 0; p < 4; p++) acc[mt][nt][p] = 0.0f;

    issue(0, 0);
    asm volatile("cp.async.commit_group;" ::: "memory");
    issue(1, 1);
    asm volatile("cp.async.commit_group;" ::: "memory");

    for (int c = 0; c < NC; c++) {
        asm volatile("cp.async.wait_group 1;" ::: "memory");
        __syncthreads();

        const __half* sA = smh + (c % 3) * (STG_B / 2);
        const __half* sB = sA + (TILE_B / 2);

#pragma unroll
        for (int s = 0; s < 2; s++) {
            const int k0 = s * 16;
            u32 a[4][4];
#pragma unroll
            for (int mt = 0; mt < 4; mt++) {
                const int r0 = wm + mt * 16 + r;
                a[mt][0] = *(const u32*)(sA + r0 * RSTRH + k0 + 2 * q);
                a[mt][1] = *(const u32*)(sA + (r0 + 8) * RSTRH + k0 + 2 * q);
                a[mt][2] = *(const u32*)(sA + r0 * RSTRH + k0 + 2 * q + 8);
                a[mt][3] = *(const u32*)(sA + (r0 + 8) * RSTRH + k0 + 2 * q + 8);
            }
#pragma unroll
            for (int nt = 0; nt < 4; nt++) {
                const int n = wn + nt * 8 + r;
                const u32 b0 = *(const u32*)(sB + n * RSTRH + k0 + 2 * q);
                const u32 b1 = *(const u32*)(sB + n * RSTRH + k0 + 2 * q + 8);
#pragma unroll
                for (int mt = 0; mt < 4; mt++)
                    mma_f16(acc[mt][nt], a[mt][0], a[mt][1], a[mt][2], a[mt][3],
                            b0, b1);
            }
        }

        if (c + 2 < NC) issue(c + 2, (c + 2) % 3);
        asm volatile("cp.async.commit_group;" ::: "memory");
    }

    // epilogue: c0,c1 -> (row, 2q+{0,1}); c2,c3 -> row+8
#pragma unroll
    for (int mt = 0; mt < 4; mt++) {
        const int r0 = m0 + wm + mt * 16 + r;
#pragma unroll
        for (int nt = 0; nt < 4; nt++) {
            const int n = wn + nt * 8 + 2 * q;
            if (r0 < N)
                *(float2*)(out + (size_t)r0 * COUT + n) =
                    make_float2(acc[mt][nt][0], acc[mt][nt][1]);
            if (r0 + 8 < N)
                *(float2*)(out + (size_t)(r0 + 8) * COUT + n) =
                    make_float2(acc[mt][nt][2], acc[mt][nt][3]);
        }
    }
}

extern "C" void kernel_launch(void* const* d_in, const int* in_sizes, int n_in,
                              void* d_out, int out_size)
{
    const float* pos   = (const float*)d_in[0];
    const float* feats = (const float*)d_in[1];
    const float* kpts  = (const float*)d_in[2];
    const float* W     = (const float*)d_in[3];
    const void*  nbrs  = d_in[4];
    float* out = (float*)d_out;

    const int N = in_sizes[1] / CIN;   // feats is [N, CIN]

    cudaFuncSetAttribute(stage3_hmma,
                         cudaFuncAttributeMaxDynamicSharedMemorySize, SMEM3);

    // order: stage12 first so ncu's fixed launch-skip samples it
    stage12_kernel<<<(N + 7) / 8, 256>>>(pos, feats, kpts, nbrs, N);

    wt_kernel<<<(KTOT * COUT + 255) / 256, 256>>>(W);

    stage3_hmma<<<(N + 127) / 128, 256, SMEM3>>>(out, N);
}

// round 16
// speedup vs baseline: 1.7346x; 1.1066x over previous
#include <cuda_runtime.h>
#include <cuda_fp16.h>
#include <cstdint>

#define KNB   32
#define KP    15
#define CIN   64
#define COUT  128
#define KTOT  (KP * CIN)     // 960
#define NMAX  65536
#define INV_SIGMA 10.0f

typedef unsigned long long u64;
typedef unsigned int u32;

__device__ __half g_wh[(size_t)NMAX * KTOT];   // weighted, fp16 (120MB)
__device__ __half g_Wth[COUT * KTOT];          // W transposed [n][k], fp16

__device__ __forceinline__ void fma2(u64& d, u64 a, u64 b) {
    asm("fma.rn.f32x2 %0, %1, %2, %0;" : "+l"(d) : "l"(a), "l"(b));
}
__device__ __forceinline__ u64 dup2(u32 x) {
    u64 r;
    asm("mov.b64 %0, {%1, %1};" : "=l"(r) : "r"(x));
    return r;
}
__device__ __forceinline__ float lo32f(u64 v) { return __uint_as_float((u32)v); }
__device__ __forceinline__ float hi32f(u64 v) { return __uint_as_float((u32)(v >> 32)); }
__device__ __forceinline__ float fsqrt_approx(float x) {
    float r;
    asm("sqrt.approx.f32 %0, %1;" : "=f"(r) : "f"(x));
    return r;
}
__device__ __forceinline__ u32 smem_u32(const void* p) {
    u32 a;
    asm("{ .reg .u64 t; cvta.to.shared.u64 t, %1; cvt.u32.u64 %0, t; }" : "=r"(a) : "l"(p));
    return a;
}
__device__ __forceinline__ void cp16(u32 dst, const void* src) {
    asm volatile("cp.async.cg.shared.global [%0], [%1], 16;" :: "r"(dst), "l"(src));
}
__device__ __forceinline__ void mma_f16(float* c, u32 a0, u32 a1, u32 a2, u32 a3,
                                        u32 b0, u32 b1) {
    asm("mma.sync.aligned.m16n8k16.row.col.f32.f16.f16.f32 "
        "{%0,%1,%2,%3}, {%4,%5,%6,%7}, {%8,%9}, {%0,%1,%2,%3};"
        : "+f"(c[0]), "+f"(c[1]), "+f"(c[2]), "+f"(c[3])
        : "r"(a0), "r"(a1), "r"(a2), "r"(a3), "r"(b0), "r"(b1));
}

// ------------------------------------------------------------ W transpose -> fp16
__global__ void wt_kernel(const float* __restrict__ W) {
    int i = blockIdx.x * 256 + threadIdx.x;     // over KTOT*COUT
    if (i < KTOT * COUT) {
        int k = i >> 7;          // KTOT index
        int n = i & 127;         // COUT index
        g_Wth[n * KTOT + k] = __float2half(W[i]);
    }
}

// ---------------------------------------------------------------- stage 1+2
// 8 warps = 8 points/block, lane owns c-pair {2l, 2l+1}.
// sInfl: per point 32 rows (j) of 16 floats (15 infl + pad0), row stride 20.
// Inner loop per j: 1 LDG.64 (feats c-pair) + 2 dup MOVs + 4 LDS.128
// (ulonglong2 -> register-adjacent kp-pair u64s, NO repacking) + 16 FFMA2.
// __launch_bounds__(256,4): R15 ran 66 regs -> 3 CTA/SM (occ 34.7%); forcing
// <=64 regs gives 4 CTA/SM. sqrt.approx kills the IEEE-sqrt inst chain.
#define ROWF 20

__global__ void __launch_bounds__(256, 4)
stage12_kernel(const float* __restrict__ pos,
               const float* __restrict__ feats,
               const float* __restrict__ kpts,
               const void*  __restrict__ nbrs,
               int N)
{
    __shared__ __align__(16) float sInfl[8][KNB * ROWF];   // 20KB
    __shared__ float sKP[KP * 3];
    __shared__ int   sNbr[8][KNB];
    __shared__ int   sIs64;

    const int tid  = threadIdx.x;
    const int wid  = tid >> 5;
    const int lane = tid & 31;

    if (tid < KP * 3) sKP[tid] = kpts[tid];
    if (tid == 0) {
        // indices < 2^16: int64 little-endian => odd 32-bit words are 0
        const int* q = (const int*)nbrs;
        int zeros = 0;
#pragma unroll
        for (int i = 0; i < 32; i++) zeros += (q[2 * i + 1] == 0) ? 1 : 0;
        sIs64 = (zeros >= 30) ? 1 : 0;
    }
    __syncthreads();

    const int n = blockIdx.x * 8 + wid;
    if (n >= N) return;

    // ---- geometry: lane = neighbor j
    int nbi;
    if (sIs64) nbi = (int)((const long long*)nbrs)[(long long)n * KNB + lane];
    else       nbi = ((const int*)nbrs)[n * KNB + lane];
    sNbr[wid][lane] = nbi;

    const float rx = pos[3 * nbi + 0] - pos[3 * n + 0];
    const float ry = pos[3 * nbi + 1] - pos[3 * n + 1];
    const float rz = pos[3 * nbi + 2] - pos[3 * n + 2];
    float v[16];
#pragma unroll
    for (int kp = 0; kp < KP; kp++) {
        const float dx = rx - sKP[3 * kp + 0];
        const float dy = ry - sKP[3 * kp + 1];
        const float dz = rz - sKP[3 * kp + 2];
        const float d2 = dx * dx + dy * dy + dz * dz;
        v[kp] = fmaxf(0.0f, 1.0f - fsqrt_approx(d2) * INV_SIGMA);
    }
    v[15] = 0.0f;
    {
        float* row = &sInfl[wid][lane * ROWF];
#pragma unroll
        for (int q4 = 0; q4 < 4; q4++)
            *(float4*)(row + q4 * 4) =
                make_float4(v[q4 * 4], v[q4 * 4 + 1], v[q4 * 4 + 2], v[q4 * 4 + 3]);
    }
    __syncwarp();

    // ---- aggregation
    u64 acc[8][2];
#pragma unroll
    for (int a = 0; a < 8; a++) { acc[a][0] = 0ULL; acc[a][1] = 0ULL; }

#pragma unroll 4
    for (int j = 0; j < KNB; j++) {
        const int nb = sNbr[wid][j];
        const u64 f = *(const u64*)(feats + (size_t)nb * CIN + 2 * lane);
        const u64 f0 = dup2((u32)f);          // {f_c0, f_c0}
        const u64 f1 = dup2((u32)(f >> 32));  // {f_c1, f_c1}
        const ulonglong2* rp = (const ulonglong2*)&sInfl[wid][j * ROWF];
#pragma unroll
        for (int q4 = 0; q4 < 4; q4++) {
            const ulonglong2 iv = rp[q4];     // broadcast LDS.128
            fma2(acc[2 * q4 + 0][0], iv.x, f0);
            fma2(acc[2 * q4 + 0][1], iv.x, f1);
            fma2(acc[2 * q4 + 1][0], iv.y, f0);
            fma2(acc[2 * q4 + 1][1], iv.y, f1);
        }
    }

    // ---- store fp16: kp=2a from lo halves, kp=2a+1 from hi halves
    __half* gp = g_wh + (size_t)n * KTOT + 2 * lane;
#pragma unroll
    for (int a = 0; a < 8; a++) {
        const __half2 h0 = __floats2half2_rn(lo32f(acc[a][0]), lo32f(acc[a][1]));
        *(__half2*)(gp + (2 * a) * CIN) = h0;
        if (a < 7) {
            const __half2 h1 = __floats2half2_rn(hi32f(acc[a][0]), hi32f(acc[a][1]));
            *(__half2*)(gp + (2 * a + 1) * CIN) = h1;
        }
    }
}

// ------------------------------------------------------------------ stage 3
// out[N,128] = g_wh[N,960] @ g_Wth^T via mma.sync m16n8k16 fp16 (f32 accum).
// CTA 128x128, K in 30 chunks of 32 halves; 3-stage cp.async pipeline.
// Tiles: 128 rows x 32 halves, row stride 40 halves (80B). Fragment half2
// loads hit bank (20*row + q + 8*s) — bijective over (r<8, q<4): conflict-free.
#define NC     30
#define RSTRH  40                 // row stride (halves)
#define TILE_B (128 * RSTRH * 2)  // bytes per tile (10240)
#define STG_B  (2 * TILE_B)       // A + B per stage (20480)
#define SMEM3  (3 * STG_B)        // 61440

__global__ void __launch_bounds__(256, 2)
stage3_hmma(float* __restrict__ out, int N)
{
    extern __shared__ __half smh[];
    const u32 sbase = smem_u32(smh);
    const int tid  = threadIdx.x;
    const int w    = tid >> 5;
    const int lane = tid & 31;
    const int wm   = (w & 1) * 64;
    const int wn   = (w >> 1) * 32;
    const int m0   = blockIdx.x * 128;
    const int q    = lane & 3;
    const int r    = lane >> 2;

    const __half* Agh = g_wh + (size_t)m0 * KTOT;

    // per chunk: A = 128 rows x 64B = 512 x 16B; 2 cp16/thread each for A and B
    auto issue = [&](int ck, int buf) {
        const u32 ab = sbase + buf * STG_B;
        const u32 bb = ab + TILE_B;
#pragma unroll
        for (int i = 0; i < 2; i++) {
            const int id  = tid + i * 256;
            const int row = id >> 2;
            const int s4  = id & 3;
            cp16(ab + row * (RSTRH * 2) + s4 * 16,
                 Agh + (size_t)row * KTOT + ck * 32 + s4 * 8);
            cp16(bb + row * (RSTRH * 2) + s4 * 16,
                 g_Wth + (size_t)row * KTOT + ck * 32 + s4 * 8);
        }
    };

    float acc[4][4][4];
#pragma unroll
    for (int mt = 0; mt < 4; mt++)
#pragma unroll
        for (int nt = 0; nt < 4; nt++)
#pragma unroll
            for (int p = 0; p < 4; p++) acc[mt][nt][p] = 0.0f;

    issue(0, 0);
    asm volatile("cp.async.commit_group;" ::: "memory");
    issue(1, 1);
    asm volatile("cp.async.commit_group;" ::: "memory");

    for (int c = 0; c < NC; c++) {
        asm volatile("cp.async.wait_group 1;" ::: "memory");
        __syncthreads();

        const __half* sA = smh + (c % 3) * (STG_B / 2);
        const __half* sB = sA + (TILE_B / 2);

#pragma unroll
        for (int s = 0; s < 2; s++) {
            const int k0 = s * 16;
            u32 a[4][4];
#pragma unroll
            for (int mt = 0; mt < 4; mt++) {
                const int r0 = wm + mt * 16 + r;
                a[mt][0] = *(const u32*)(sA + r0 * RSTRH + k0 + 2 * q);
                a[mt][1] = *(const u32*)(sA + (r0 + 8) * RSTRH + k0 + 2 * q);
                a[mt][2] = *(const u32*)(sA + r0 * RSTRH + k0 + 2 * q + 8);
                a[mt][3] = *(const u32*)(sA + (r0 + 8) * RSTRH + k0 + 2 * q + 8);
            }
#pragma unroll
            for (int nt = 0; nt < 4; nt++) {
                const int n = wn + nt * 8 + r;
                const u32 b0 = *(const u32*)(sB + n * RSTRH + k0 + 2 * q);
                const u32 b1 = *(const u32*)(sB + n * RSTRH + k0 + 2 * q + 8);
#pragma unroll
                for (int mt = 0; mt < 4; mt++)
                    mma_f16(acc[mt][nt], a[mt][0], a[mt][1], a[mt][2], a[mt][3],
                            b0, b1);
            }
        }

        if (c + 2 < NC) issue(c + 2, (c + 2) % 3);
        asm volatile("cp.async.commit_group;" ::: "memory");
    }

    // epilogue: c0,c1 -> (row, 2q+{0,1}); c2,c3 -> row+8
#pragma unroll
    for (int mt = 0; mt < 4; mt++) {
        const int r0 = m0 + wm + mt * 16 + r;
#pragma unroll
        for (int nt = 0; nt < 4; nt++) {
            const int n = wn + nt * 8 + 2 * q;
            if (r0 < N)
                *(float2*)(out + (size_t)r0 * COUT + n) =
                    make_float2(acc[mt][nt][0], acc[mt][nt][1]);
            if (r0 + 8 < N)
                *(float2*)(out + (size_t)(r0 + 8) * COUT + n) =
                    make_float2(acc[mt][nt][2], acc[mt][nt][3]);
        }
    }
}

extern "C" void kernel_launch(void* const* d_in, const int* in_sizes, int n_in,
                              void* d_out, int out_size)
{
    const float* pos   = (const float*)d_in[0];
    const float* feats = (const float*)d_in[1];
    const float* kpts  = (const float*)d_in[2];
    const float* W     = (const float*)d_in[3];
    const void*  nbrs  = d_in[4];
    float* out = (float*)d_out;

    const int N = in_sizes[1] / CIN;   // feats is [N, CIN]

    cudaFuncSetAttribute(stage3_hmma,
                         cudaFuncAttributeMaxDynamicSharedMemorySize, SMEM3);

    // order: stage12 first so ncu's fixed launch-skip samples it
    stage12_kernel<<<(N + 7) / 8, 256>>>(pos, feats, kpts, nbrs, N);

    wt_kernel<<<(KTOT * COUT + 255) / 256, 256>>>(W);

    stage3_hmma<<<(N + 127) / 128, 256, SMEM3>>>(out, N);
}